// round 15
// baseline (speedup 1.0000x reference)
#include <cuda_runtime.h>
#include <math.h>

// LIF scan: B=8, T=64, C=64, H=32, W=32. ~268 MB streaming, LTS-floor.
// HYBRID body, combining both measured wins:
//  - loads batched 4-wide per chunk (chunked bodies measured 0.7us faster
//    in-kernel via front-issued independent LDG.128)
//  - stores issued per-t inside the chunk (rolling bodies measured ~3us
//    lower replay-seam overhead: no trailing store burst at kernel end)
// Grid 512x256 = the measured bench-best config (48.4us).

#define B_ 8
#define T_ 64
#define CHW_ 65536              // 64*32*32
#define CHW4_ (CHW_ / 4)        // 16384 float4 per (b,t) slab
#define N4_ (B_ * CHW4_)        // 131072 threads
#define CHUNK_ 4

__global__ __launch_bounds__(256) void lif_scan_kernel(
    const float4* __restrict__ x,        // [B*T*CHW4] float4
    const float4* __restrict__ vth_raw,  // [CHW4]
    const float4* __restrict__ decay_raw,// [CHW4]
    const float* __restrict__ hp_v_m,
    const float* __restrict__ hp_v_s,
    const float* __restrict__ hp_d_m,
    const float* __restrict__ hp_d_s,
    float4* __restrict__ out)            // [B*T*CHW4] float4
{
    int tid = blockIdx.x * blockDim.x + threadIdx.x;
    if (tid >= N4_) return;

    int b = tid >> 14;          // tid / CHW4_
    int j = tid & (CHW4_ - 1);  // tid % CHW4_

    float vm = *hp_v_m, vs = *hp_v_s;
    float dm = *hp_d_m, ds = *hp_d_s;

    float4 vr = vth_raw[j];
    float4 dr = decay_raw[j];

    // vth = softplus(vr*vs + vm) + 0.5, numerically stable
    float vth[4], dec[4];
    {
        float z[4] = {vr.x * vs + vm, vr.y * vs + vm, vr.z * vs + vm, vr.w * vs + vm};
        float d[4] = {dr.x * ds + dm, dr.y * ds + dm, dr.z * ds + dm, dr.w * ds + dm};
        #pragma unroll
        for (int k = 0; k < 4; k++) {
            float zz = z[k];
            float sp = (zz > 20.0f) ? zz : log1pf(__expf(zz));
            vth[k] = sp + 0.5f;
            float sg = 1.0f / (1.0f + __expf(-d[k]));
            dec[k] = fminf(fmaxf(sg, 0.0f), 0.99f);
        }
    }

    const float4* xp = x + (size_t)b * T_ * CHW4_ + j;
    float4* op = out + (size_t)b * T_ * CHW4_ + j;

    float v[4] = {0.f, 0.f, 0.f, 0.f};

    #pragma unroll
    for (int t0 = 0; t0 < T_; t0 += CHUNK_) {
        // Batch 4 independent LDG.128 (front-issued back-to-back).
        float4 xs[CHUNK_];
        #pragma unroll
        for (int i = 0; i < CHUNK_; i++)
            xs[i] = xp[(size_t)(t0 + i) * CHW4_];

        // Compute AND store each t immediately (incremental store drain).
        #pragma unroll
        for (int i = 0; i < CHUNK_; i++) {
            float xv[4] = {xs[i].x, xs[i].y, xs[i].z, xs[i].w};
            float s[4];
            #pragma unroll
            for (int k = 0; k < 4; k++) {
                float vv = fmaf(v[k], dec[k], xv[k]);
                float sk = (vv - vth[k] > 0.0f) ? 1.0f : 0.0f;
                v[k] = vv - sk * vth[k];
                s[k] = sk;
            }
            op[(size_t)(t0 + i) * CHW4_] = make_float4(s[0], s[1], s[2], s[3]);
        }
    }
}

extern "C" void kernel_launch(void* const* d_in, const int* in_sizes, int n_in,
                              void* d_out, int out_size)
{
    const float4* x         = (const float4*)d_in[0];
    const float4* vth_raw   = (const float4*)d_in[1];
    const float4* decay_raw = (const float4*)d_in[2];
    const float*  hp_v_m    = (const float*)d_in[3];
    const float*  hp_v_s    = (const float*)d_in[4];
    const float*  hp_d_m    = (const float*)d_in[5];
    const float*  hp_d_s    = (const float*)d_in[6];
    // d_in[7] = hp_alpha, unused in forward
    float4* out = (float4*)d_out;

    int threads = 256;
    int blocks = (N4_ + threads - 1) / threads;  // 512
    lif_scan_kernel<<<blocks, threads>>>(x, vth_raw, decay_raw,
                                         hp_v_m, hp_v_s, hp_d_m, hp_d_s, out);
}

// round 16
// speedup vs baseline: 1.1184x; 1.1184x over previous
#include <cuda_runtime.h>
#include <math.h>

// LIF scan: B=8, T=64, C=64, H=32, W=32.
// x: [B, T, C, H, W] f32; vth_raw, decay_raw: [C,H,W] f32; 5 f32 scalars.
// out: spikes [B, T, C, H, W] f32.
//
// Parallel over (b, chw/4) with float4 vectorization; sequential over T in
// registers. Memory-bound streaming: ~268 MB total traffic, LTS-saturated
// at ~6.7 TB/s (floor confirmed 5x at ncu 40.1-40.8us).
//
// TERMINAL FORM -- measured bench best (48.4/49.2us across two holds; all
// 9 other structures 51.2-53.2us). Rolling per-t store keeps replay-seam
// overhead low (~7.5-8us vs 9.5-13us for burst-store bodies); ptxas's
// schedule is bistable and only the pure rolling/chunked attractors are
// good -- hybrids measured worse than both.

#define B_ 8
#define T_ 64
#define CHW_ 65536              // 64*32*32
#define CHW4_ (CHW_ / 4)        // 16384 float4 per (b,t) slab
#define N4_ (B_ * CHW4_)        // 131072 threads

__global__ __launch_bounds__(256) void lif_scan_kernel(
    const float4* __restrict__ x,        // [B*T*CHW4] float4
    const float4* __restrict__ vth_raw,  // [CHW4]
    const float4* __restrict__ decay_raw,// [CHW4]
    const float* __restrict__ hp_v_m,
    const float* __restrict__ hp_v_s,
    const float* __restrict__ hp_d_m,
    const float* __restrict__ hp_d_s,
    float4* __restrict__ out)            // [B*T*CHW4] float4
{
    int tid = blockIdx.x * blockDim.x + threadIdx.x;
    if (tid >= N4_) return;

    int b = tid >> 14;          // tid / CHW4_
    int j = tid & (CHW4_ - 1);  // tid % CHW4_

    float vm = *hp_v_m, vs = *hp_v_s;
    float dm = *hp_d_m, ds = *hp_d_s;

    float4 vr = vth_raw[j];
    float4 dr = decay_raw[j];

    // vth = softplus(vr*vs + vm) + 0.5, numerically stable
    float vth[4], dec[4];
    {
        float z[4] = {vr.x * vs + vm, vr.y * vs + vm, vr.z * vs + vm, vr.w * vs + vm};
        float d[4] = {dr.x * ds + dm, dr.y * ds + dm, dr.z * ds + dm, dr.w * ds + dm};
        #pragma unroll
        for (int k = 0; k < 4; k++) {
            float zz = z[k];
            // softplus: log1p(exp(z)); for large z -> z (avoids overflow)
            float sp = (zz > 20.0f) ? zz : log1pf(__expf(zz));
            vth[k] = sp + 0.5f;
            float sg = 1.0f / (1.0f + __expf(-d[k]));
            dec[k] = fminf(fmaxf(sg, 0.0f), 0.99f);
        }
    }

    const float4* xp = x + (size_t)b * T_ * CHW4_ + j;
    float4* op = out + (size_t)b * T_ * CHW4_ + j;

    float v[4] = {0.f, 0.f, 0.f, 0.f};

    #pragma unroll 8
    for (int t = 0; t < T_; t++) {
        float4 xt = xp[(size_t)t * CHW4_];
        float xv[4] = {xt.x, xt.y, xt.z, xt.w};
        float s[4];
        #pragma unroll
        for (int k = 0; k < 4; k++) {
            float vv = fmaf(v[k], dec[k], xv[k]);
            float sk = (vv - vth[k] > 0.0f) ? 1.0f : 0.0f;
            v[k] = vv - sk * vth[k];
            s[k] = sk;
        }
        float4 so = make_float4(s[0], s[1], s[2], s[3]);
        op[(size_t)t * CHW4_] = so;
    }
}

extern "C" void kernel_launch(void* const* d_in, const int* in_sizes, int n_in,
                              void* d_out, int out_size)
{
    const float4* x         = (const float4*)d_in[0];
    const float4* vth_raw   = (const float4*)d_in[1];
    const float4* decay_raw = (const float4*)d_in[2];
    const float*  hp_v_m    = (const float*)d_in[3];
    const float*  hp_v_s    = (const float*)d_in[4];
    const float*  hp_d_m    = (const float*)d_in[5];
    const float*  hp_d_s    = (const float*)d_in[6];
    // d_in[7] = hp_alpha, unused in forward
    float4* out = (float4*)d_out;

    int threads = 256;
    int blocks = (N4_ + threads - 1) / threads;  // 512
    lif_scan_kernel<<<blocks, threads>>>(x, vth_raw, decay_raw,
                                         hp_v_m, hp_v_s, hp_d_m, hp_d_s, out);
}